// round 1
// baseline (speedup 1.0000x reference)
#include <cuda_runtime.h>
#include <cstdint>

// Problem constants
#define BB     4096
#define D_IN   128
#define HID    200
#define DIMV   256
#define MM     32

// Scratch (device globals — no allocation allowed)
__device__ float g_H1[BB * HID];
__device__ float g_H2[BB * HID];
__device__ float g_Y [BB * DIMV];
__device__ float g_Q [MM * DIMV];

// ---------------------------------------------------------------------------
// Setup: G = A A^T + 1e-6 I (32x32), Gauss-Jordan inverse, Q = G^{-1} A
// Single block, 1024 threads.
// ---------------------------------------------------------------------------
__global__ void setup_kernel(const float* __restrict__ A)
{
    __shared__ float G[32][65];   // augmented [G | I], padded
    __shared__ float fcol[32];
    const int t = threadIdx.x;
    const int i = t >> 5;
    const int j = t & 31;

    // Gram matrix
    float s = 0.f;
    for (int k = 0; k < DIMV; k++)
        s += A[i * DIMV + k] * A[j * DIMV + k];
    G[i][j]      = s + (i == j ? 1e-6f : 0.f);
    G[i][j + 32] = (i == j) ? 1.f : 0.f;
    __syncthreads();

    // Gauss-Jordan (SPD, no pivoting)
    for (int k = 0; k < 32; k++) {
        if (j == 0) fcol[i] = G[i][k];
        __syncthreads();
        if (i == k) {
            float inv = 1.f / fcol[k];
            G[k][j]      *= inv;
            G[k][j + 32] *= inv;
        }
        __syncthreads();
        if (i != k) {
            float f = fcol[i];
            G[i][j]      -= f * G[k][j];
            G[i][j + 32] -= f * G[k][j + 32];
        }
        __syncthreads();
    }

    // Q = Ginv @ A  [32 x 256]
    for (int r = 0; r < 8; r++) {
        int idx = t + r * 1024;
        int m = idx >> 8;
        int d = idx & 255;
        float acc = 0.f;
        for (int k = 0; k < 32; k++)
            acc += G[m][32 + k] * A[k * DIMV + d];
        g_Q[m * DIMV + d] = acc;
    }
}

// ---------------------------------------------------------------------------
// Generic tiled GEMM: Y[M,N] = act(X[M,K] @ W[K,N] + bias)
// BM=BN=64, BK=16, 256 threads, 4x4 per thread.
// ---------------------------------------------------------------------------
template<bool RELU>
__global__ __launch_bounds__(256)
void gemm_bias_kernel(const float* __restrict__ X, const float* __restrict__ W,
                      const float* __restrict__ bias, float* __restrict__ Y,
                      int Mrows, int N, int K)
{
    __shared__ float Xs[16][68];
    __shared__ float Ws[16][68];
    const int t  = threadIdx.x;
    const int tx = t & 15, ty = t >> 4;
    const int row0 = blockIdx.y * 64;
    const int col0 = blockIdx.x * 64;

    float acc[4][4];
#pragma unroll
    for (int i = 0; i < 4; i++)
#pragma unroll
        for (int j = 0; j < 4; j++) acc[i][j] = 0.f;

    for (int k0 = 0; k0 < K; k0 += 16) {
        // X tile: 64 rows x 16 k
        {
            int r = t >> 2, q = (t & 3) * 4;
#pragma unroll
            for (int i = 0; i < 4; i++) {
                int kk = q + i;
                float v = 0.f;
                if (k0 + kk < K) v = X[(size_t)(row0 + r) * K + k0 + kk];
                Xs[kk][r] = v;
            }
        }
        // W tile: 16 k x 64 cols
        {
            int kk = t >> 4, c = (t & 15) * 4;
#pragma unroll
            for (int j = 0; j < 4; j++) {
                float v = 0.f;
                if (k0 + kk < K && col0 + c + j < N)
                    v = W[(size_t)(k0 + kk) * N + col0 + c + j];
                Ws[kk][c + j] = v;
            }
        }
        __syncthreads();
#pragma unroll
        for (int kk = 0; kk < 16; kk++) {
            float a[4], bv[4];
#pragma unroll
            for (int i = 0; i < 4; i++) a[i]  = Xs[kk][ty * 4 + i];
#pragma unroll
            for (int j = 0; j < 4; j++) bv[j] = Ws[kk][tx * 4 + j];
#pragma unroll
            for (int i = 0; i < 4; i++)
#pragma unroll
                for (int j = 0; j < 4; j++)
                    acc[i][j] += a[i] * bv[j];
        }
        __syncthreads();
    }

#pragma unroll
    for (int i = 0; i < 4; i++) {
        int rr = row0 + ty * 4 + i;
        if (rr < Mrows) {
#pragma unroll
            for (int j = 0; j < 4; j++) {
                int cc = col0 + tx * 4 + j;
                if (cc < N) {
                    float v = acc[i][j] + bias[cc];
                    if (RELU) v = fmaxf(v, 0.f);
                    Y[(size_t)rr * N + cc] = v;
                }
            }
        }
    }
}

// ---------------------------------------------------------------------------
// Iteration kernel: warp-per-2-rows, z in registers, A/Q in shared.
// ---------------------------------------------------------------------------
__device__ __forceinline__ void compute_u(const float4* __restrict__ As4,
                                          const float4* __restrict__ Qs4,
                                          const float z0[8], const float z1[8],
                                          float bc0, float bc1, int lane,
                                          float u0[8], float u1[8])
{
    // GEMM1 partials: p[m] = sum over this lane's 8 z components
    float p0[32], p1[32];
#pragma unroll
    for (int m = 0; m < 32; m++) {
        float4 a  = As4[m * 64 + 2 * lane];
        float4 a2 = As4[m * 64 + 2 * lane + 1];
        p0[m] = z0[0]*a.x + z0[1]*a.y + z0[2]*a.z + z0[3]*a.w
              + z0[4]*a2.x + z0[5]*a2.y + z0[6]*a2.z + z0[7]*a2.w;
        p1[m] = z1[0]*a.x + z1[1]*a.y + z1[2]*a.z + z1[3]*a.w
              + z1[4]*a2.x + z1[5]*a2.y + z1[6]*a2.z + z1[7]*a2.w;
    }

    // Butterfly transpose-reduce: lane l ends holding r[l] in p[0]
#pragma unroll
    for (int s = 16; s >= 1; s >>= 1) {
#pragma unroll
        for (int i = 0; i < s; i++) {
            {
                float aa = p0[i], bb = p0[i + s];
                float send = (lane & s) ? aa : bb;
                float recv = __shfl_xor_sync(0xffffffffu, send, s);
                p0[i] = ((lane & s) ? bb : aa) + recv;
            }
            {
                float aa = p1[i], bb = p1[i + s];
                float send = (lane & s) ? aa : bb;
                float recv = __shfl_xor_sync(0xffffffffu, send, s);
                p1[i] = ((lane & s) ? bb : aa) + recv;
            }
        }
    }
    float r0 = p0[0] - bc0;
    float r1 = p1[0] - bc1;

    // GEMM2: u = z - r @ Q
    float acc0[8], acc1[8];
#pragma unroll
    for (int j = 0; j < 8; j++) { acc0[j] = 0.f; acc1[j] = 0.f; }
#pragma unroll
    for (int m = 0; m < 32; m++) {
        float rm0 = __shfl_sync(0xffffffffu, r0, m);
        float rm1 = __shfl_sync(0xffffffffu, r1, m);
        float4 q  = Qs4[m * 64 + 2 * lane];
        float4 q2 = Qs4[m * 64 + 2 * lane + 1];
        acc0[0] += rm0 * q.x;  acc0[1] += rm0 * q.y;
        acc0[2] += rm0 * q.z;  acc0[3] += rm0 * q.w;
        acc0[4] += rm0 * q2.x; acc0[5] += rm0 * q2.y;
        acc0[6] += rm0 * q2.z; acc0[7] += rm0 * q2.w;
        acc1[0] += rm1 * q.x;  acc1[1] += rm1 * q.y;
        acc1[2] += rm1 * q.z;  acc1[3] += rm1 * q.w;
        acc1[4] += rm1 * q2.x; acc1[5] += rm1 * q2.y;
        acc1[6] += rm1 * q2.z; acc1[7] += rm1 * q2.w;
    }
#pragma unroll
    for (int j = 0; j < 8; j++) {
        u0[j] = z0[j] - acc0[j];
        u1[j] = z1[j] - acc1[j];
    }
}

__global__ __launch_bounds__(256, 2)
void iter_kernel(const float* __restrict__ bmat,
                 const float* __restrict__ A,
                 const int*   __restrict__ n_iter_ptr,
                 float* __restrict__ out)
{
    extern __shared__ float smem[];
    float* As = smem;          // 32*256
    float* Qs = smem + 8192;   // 32*256
    const int t = threadIdx.x;
    for (int i = t; i < 8192; i += 256) {
        As[i] = A[i];
        Qs[i] = g_Q[i];
    }
    __syncthreads();

    const int lane = t & 31;
    const int w    = t >> 5;
    const int pair = blockIdx.x * 8 + w;          // 0..2047
    const int row0 = pair * 2;
    const int row1 = row0 + 1;

    const float4* As4 = (const float4*)As;
    const float4* Qs4 = (const float4*)Qs;

    // Load z0/z1 from MLP output
    float z0[8], z1[8];
    {
        const float4* y0 = (const float4*)(g_Y + (size_t)row0 * DIMV);
        const float4* y1 = (const float4*)(g_Y + (size_t)row1 * DIMV);
        float4 a = y0[2 * lane], b = y0[2 * lane + 1];
        z0[0]=a.x; z0[1]=a.y; z0[2]=a.z; z0[3]=a.w;
        z0[4]=b.x; z0[5]=b.y; z0[6]=b.z; z0[7]=b.w;
        float4 c = y1[2 * lane], d = y1[2 * lane + 1];
        z1[0]=c.x; z1[1]=c.y; z1[2]=c.z; z1[3]=c.w;
        z1[4]=d.x; z1[5]=d.y; z1[6]=d.z; z1[7]=d.w;
    }
    const float bc0 = bmat[(size_t)row0 * MM + lane];
    const float bc1 = bmat[(size_t)row1 * MM + lane];
    const int niter = *n_iter_ptr;

    float u0[8], u1[8];
    for (int it = 0; it < niter; ++it) {
        compute_u(As4, Qs4, z0, z1, bc0, bc1, lane, u0, u1);
#pragma unroll
        for (int j = 0; j < 8; j++) {
            float v0 = fminf(fmaxf(2.f * u0[j] - z0[j], 0.f), 1.f);
            z0[j] += 1.7f * (v0 - u0[j]);
            float v1 = fminf(fmaxf(2.f * u1[j] - z1[j], 0.f), 1.f);
            z1[j] += 1.7f * (v1 - u1[j]);
        }
    }

    // Final projection: out = p_aff(z)
    compute_u(As4, Qs4, z0, z1, bc0, bc1, lane, u0, u1);
    {
        float4* o0 = (float4*)(out + (size_t)row0 * DIMV);
        float4* o1 = (float4*)(out + (size_t)row1 * DIMV);
        float4 a; a.x=u0[0]; a.y=u0[1]; a.z=u0[2]; a.w=u0[3];
        float4 b; b.x=u0[4]; b.y=u0[5]; b.z=u0[6]; b.w=u0[7];
        o0[2 * lane] = a; o0[2 * lane + 1] = b;
        float4 c; c.x=u1[0]; c.y=u1[1]; c.z=u1[2]; c.w=u1[3];
        float4 d; d.x=u1[4]; d.y=u1[5]; d.z=u1[6]; d.w=u1[7];
        o1[2 * lane] = c; o1[2 * lane + 1] = d;
    }
}

// ---------------------------------------------------------------------------
// Launch
// ---------------------------------------------------------------------------
extern "C" void kernel_launch(void* const* d_in, const int* in_sizes, int n_in,
                              void* d_out, int out_size)
{
    const float* x   = (const float*)d_in[0];
    const float* b   = (const float*)d_in[1];
    const float* W1  = (const float*)d_in[2];
    const float* b1  = (const float*)d_in[3];
    const float* W2  = (const float*)d_in[4];
    const float* b2  = (const float*)d_in[5];
    const float* W3  = (const float*)d_in[6];
    const float* b3  = (const float*)d_in[7];
    const float* A   = (const float*)d_in[8];
    const int* n_it  = (const int*)d_in[10];
    float* out = (float*)d_out;

    // Setup: Q = (A A^T + eps I)^{-1} A
    setup_kernel<<<1, 1024>>>(A);

    float* h1; cudaGetSymbolAddress((void**)&h1, g_H1);
    float* h2; cudaGetSymbolAddress((void**)&h2, g_H2);
    float* y;  cudaGetSymbolAddress((void**)&y,  g_Y);

    // MLP
    gemm_bias_kernel<true ><<<dim3((HID  + 63) / 64, BB / 64), 256>>>(x,  W1, b1, h1, BB, HID,  D_IN);
    gemm_bias_kernel<true ><<<dim3((HID  + 63) / 64, BB / 64), 256>>>(h1, W2, b2, h2, BB, HID,  HID);
    gemm_bias_kernel<false><<<dim3((DIMV + 63) / 64, BB / 64), 256>>>(h2, W3, b3, y,  BB, DIMV, HID);

    // Iterations
    cudaFuncSetAttribute(iter_kernel, cudaFuncAttributeMaxDynamicSharedMemorySize, 65536);
    iter_kernel<<<BB / 16, 256, 65536>>>(b, A, n_it, out);
}

// round 2
// speedup vs baseline: 1.8040x; 1.8040x over previous
#include <cuda_runtime.h>
#include <cstdint>
#include <cstring>

// Problem constants
#define BB     4096
#define D_IN   128
#define HID    200
#define DIMV   256
#define MM     32

// Scratch (device globals — no allocation allowed)
__device__ float g_H1[BB * HID];
__device__ float g_H2[BB * HID];
__device__ float g_Y [BB * DIMV];
__device__ float g_Q [MM * DIMV];

// ---------------------------------------------------------------------------
// Packed f32x2 helpers (sm_100+; ptxas never auto-fuses these)
// ---------------------------------------------------------------------------
static __device__ __forceinline__ float2 f2fma(float2 a, float2 b, float2 c) {
    unsigned long long ua, ub, uc, ud;
    memcpy(&ua, &a, 8); memcpy(&ub, &b, 8); memcpy(&uc, &c, 8);
    asm("fma.rn.f32x2 %0, %1, %2, %3;" : "=l"(ud) : "l"(ua), "l"(ub), "l"(uc));
    float2 r; memcpy(&r, &ud, 8); return r;
}
static __device__ __forceinline__ float2 f2mul(float2 a, float2 b) {
    unsigned long long ua, ub, ud;
    memcpy(&ua, &a, 8); memcpy(&ub, &b, 8);
    asm("mul.rn.f32x2 %0, %1, %2;" : "=l"(ud) : "l"(ua), "l"(ub));
    float2 r; memcpy(&r, &ud, 8); return r;
}

// ---------------------------------------------------------------------------
// Setup: G = A A^T + 1e-6 I (32x32), Gauss-Jordan inverse, Q = G^{-1} A
// ---------------------------------------------------------------------------
__global__ void setup_kernel(const float* __restrict__ A)
{
    __shared__ float G[32][65];
    __shared__ float fcol[32];
    const int t = threadIdx.x;
    const int i = t >> 5;
    const int j = t & 31;

    float s = 0.f;
    for (int k = 0; k < DIMV; k++)
        s += A[i * DIMV + k] * A[j * DIMV + k];
    G[i][j]      = s + (i == j ? 1e-6f : 0.f);
    G[i][j + 32] = (i == j) ? 1.f : 0.f;
    __syncthreads();

    for (int k = 0; k < 32; k++) {
        if (j == 0) fcol[i] = G[i][k];
        __syncthreads();
        if (i == k) {
            float inv = 1.f / fcol[k];
            G[k][j]      *= inv;
            G[k][j + 32] *= inv;
        }
        __syncthreads();
        if (i != k) {
            float f = fcol[i];
            G[i][j]      -= f * G[k][j];
            G[i][j + 32] -= f * G[k][j + 32];
        }
        __syncthreads();
    }

    for (int r = 0; r < 8; r++) {
        int idx = t + r * 1024;
        int m = idx >> 8;
        int d = idx & 255;
        float acc = 0.f;
        for (int k = 0; k < 32; k++)
            acc += G[m][32 + k] * A[k * DIMV + d];
        g_Q[m * DIMV + d] = acc;
    }
}

// ---------------------------------------------------------------------------
// Tiled GEMM: Y[M,N] = act(X[M,K] @ W[K,N] + bias)
// ---------------------------------------------------------------------------
template<bool RELU>
__global__ __launch_bounds__(256)
void gemm_bias_kernel(const float* __restrict__ X, const float* __restrict__ W,
                      const float* __restrict__ bias, float* __restrict__ Y,
                      int Mrows, int N, int K)
{
    __shared__ float Xs[16][68];
    __shared__ float Ws[16][68];
    const int t  = threadIdx.x;
    const int tx = t & 15, ty = t >> 4;
    const int row0 = blockIdx.y * 64;
    const int col0 = blockIdx.x * 64;

    float acc[4][4];
#pragma unroll
    for (int i = 0; i < 4; i++)
#pragma unroll
        for (int j = 0; j < 4; j++) acc[i][j] = 0.f;

    for (int k0 = 0; k0 < K; k0 += 16) {
        {
            int r = t >> 2, q = (t & 3) * 4;
#pragma unroll
            for (int i = 0; i < 4; i++) {
                int kk = q + i;
                float v = 0.f;
                if (k0 + kk < K) v = X[(size_t)(row0 + r) * K + k0 + kk];
                Xs[kk][r] = v;
            }
        }
        {
            int kk = t >> 4, c = (t & 15) * 4;
#pragma unroll
            for (int j = 0; j < 4; j++) {
                float v = 0.f;
                if (k0 + kk < K && col0 + c + j < N)
                    v = W[(size_t)(k0 + kk) * N + col0 + c + j];
                Ws[kk][c + j] = v;
            }
        }
        __syncthreads();
#pragma unroll
        for (int kk = 0; kk < 16; kk++) {
            float a[4], bv[4];
#pragma unroll
            for (int i = 0; i < 4; i++) a[i]  = Xs[kk][ty * 4 + i];
#pragma unroll
            for (int j = 0; j < 4; j++) bv[j] = Ws[kk][tx * 4 + j];
#pragma unroll
            for (int i = 0; i < 4; i++)
#pragma unroll
                for (int j = 0; j < 4; j++)
                    acc[i][j] += a[i] * bv[j];
        }
        __syncthreads();
    }

#pragma unroll
    for (int i = 0; i < 4; i++) {
        int rr = row0 + ty * 4 + i;
        if (rr < Mrows) {
#pragma unroll
            for (int j = 0; j < 4; j++) {
                int cc = col0 + tx * 4 + j;
                if (cc < N) {
                    float v = acc[i][j] + bias[cc];
                    if (RELU) v = fmaxf(v, 0.f);
                    Y[(size_t)rr * N + cc] = v;
                }
            }
        }
    }
}

// ---------------------------------------------------------------------------
// Iteration kernel: warp-per-4-rows, z in registers, f32x2 math.
// Lane mapping: lane owns d = {4*lane..4*lane+3} and {128+4*lane..128+4*lane+3}.
// Smem layout: row-major A[m][d], float4 index m*64 + lane (lo) / m*64+32+lane (hi)
// -> consecutive lanes hit consecutive 16B: conflict-free LDS.128.
// ---------------------------------------------------------------------------
__global__ __launch_bounds__(128)
void iter_kernel(const float* __restrict__ bmat,
                 const float* __restrict__ A,
                 const int*   __restrict__ n_iter_ptr,
                 float* __restrict__ out)
{
    extern __shared__ float smem[];
    float* As = smem;          // 32*256
    float* Qs = smem + 8192;   // 32*256
    const int t = threadIdx.x;
    for (int i = t; i < 8192; i += 128) {
        As[i] = A[i];
        Qs[i] = g_Q[i];
    }
    __syncthreads();

    const int lane = t & 31;
    const int w    = t >> 5;
    const int rowbase = blockIdx.x * 16 + w * 4;  // 4 rows per warp

    const float4* As4 = (const float4*)As;
    const float4* Qs4 = (const float4*)Qs;

    // z[r][k]: k=0,1 -> d = 4*lane + {0,1},{2,3};  k=2,3 -> d = 128+4*lane + {0,1},{2,3}
    float2 z[4][4];
#pragma unroll
    for (int r = 0; r < 4; r++) {
        const float4* y = (const float4*)(g_Y + (size_t)(rowbase + r) * DIMV);
        float4 lo = y[lane];
        float4 hi = y[32 + lane];
        z[r][0] = make_float2(lo.x, lo.y); z[r][1] = make_float2(lo.z, lo.w);
        z[r][2] = make_float2(hi.x, hi.y); z[r][3] = make_float2(hi.z, hi.w);
    }

    // nc[r][k] = -(b_row @ Q)[d(k)]  (iteration-invariant; acc starts here)
    float2 nc[4][4];
#pragma unroll
    for (int r = 0; r < 4; r++)
#pragma unroll
        for (int k = 0; k < 4; k++) nc[r][k] = make_float2(0.f, 0.f);
    for (int m = 0; m < MM; m++) {
        float4 qlo = Qs4[m * 64 + lane];
        float4 qhi = Qs4[m * 64 + 32 + lane];
        float2 q0 = make_float2(qlo.x, qlo.y), q1 = make_float2(qlo.z, qlo.w);
        float2 q2 = make_float2(qhi.x, qhi.y), q3 = make_float2(qhi.z, qhi.w);
#pragma unroll
        for (int r = 0; r < 4; r++) {
            float bv = -bmat[(size_t)(rowbase + r) * MM + m];
            float2 b2 = make_float2(bv, bv);
            nc[r][0] = f2fma(b2, q0, nc[r][0]);
            nc[r][1] = f2fma(b2, q1, nc[r][1]);
            nc[r][2] = f2fma(b2, q2, nc[r][2]);
            nc[r][3] = f2fma(b2, q3, nc[r][3]);
        }
    }

    const int niter = *n_iter_ptr;
    const unsigned FULL = 0xffffffffu;
    const float2 NEG1 = make_float2(-1.f, -1.f);

    float2 u[4][4];

    for (int it = 0; ; ++it) {
        // ---- GEMM1: r_m = (A z)_m, m-halved transpose-reduce ----
        float r_red[4];
#pragma unroll
        for (int half = 0; half < 2; half++) {
            float ph[4][16];
#pragma unroll
            for (int i = 0; i < 16; i++) {
                const int m = half * 16 + i;
                float4 alo = As4[m * 64 + lane];
                float4 ahi = As4[m * 64 + 32 + lane];
                float2 a0 = make_float2(alo.x, alo.y), a1 = make_float2(alo.z, alo.w);
                float2 a2 = make_float2(ahi.x, ahi.y), a3 = make_float2(ahi.z, ahi.w);
#pragma unroll
                for (int r = 0; r < 4; r++) {
                    float2 pp = f2mul(z[r][0], a0);
                    pp = f2fma(z[r][1], a1, pp);
                    pp = f2fma(z[r][2], a2, pp);
                    pp = f2fma(z[r][3], a3, pp);
                    ph[r][i] = pp.x + pp.y;
                }
            }
            // butterfly transpose-reduce of 16 values within each 16-lane group
#pragma unroll
            for (int s = 8; s >= 1; s >>= 1) {
#pragma unroll
                for (int i = 0; i < s; i++) {
#pragma unroll
                    for (int r = 0; r < 4; r++) {
                        float aa = ph[r][i], bb = ph[r][i + s];
                        float send = (lane & s) ? aa : bb;
                        float recv = __shfl_xor_sync(FULL, send, s);
                        ph[r][i] = ((lane & s) ? bb : aa) + recv;
                    }
                }
            }
            // combine the two 16-lane groups; every lane holds r[half*16 + (lane&15)]
#pragma unroll
            for (int r = 0; r < 4; r++) {
                float tt = ph[r][0];
                tt += __shfl_xor_sync(FULL, tt, 16);
                if (half == 0) r_red[r] = tt;
                else           r_red[r] = (lane & 16) ? tt : r_red[r];
            }
        }
        // now lane l holds r_red[r] = (A z_r)_l

        // ---- GEMM2: acc = -c + sum_m r_m Q[m,:];  u = z - acc ----
        float2 acc[4][4];
#pragma unroll
        for (int r = 0; r < 4; r++)
#pragma unroll
            for (int k = 0; k < 4; k++) acc[r][k] = nc[r][k];
#pragma unroll
        for (int m = 0; m < MM; m++) {
            float4 qlo = Qs4[m * 64 + lane];
            float4 qhi = Qs4[m * 64 + 32 + lane];
            float2 q0 = make_float2(qlo.x, qlo.y), q1 = make_float2(qlo.z, qlo.w);
            float2 q2 = make_float2(qhi.x, qhi.y), q3 = make_float2(qhi.z, qhi.w);
#pragma unroll
            for (int r = 0; r < 4; r++) {
                float rm = __shfl_sync(FULL, r_red[r], m);
                float2 rm2 = make_float2(rm, rm);
                acc[r][0] = f2fma(rm2, q0, acc[r][0]);
                acc[r][1] = f2fma(rm2, q1, acc[r][1]);
                acc[r][2] = f2fma(rm2, q2, acc[r][2]);
                acc[r][3] = f2fma(rm2, q3, acc[r][3]);
            }
        }
#pragma unroll
        for (int r = 0; r < 4; r++)
#pragma unroll
            for (int k = 0; k < 4; k++)
                u[r][k] = f2fma(acc[r][k], NEG1, z[r][k]);   // u = z - acc

        if (it == niter) break;

        // ---- z update: v = clip(2u - z, 0, 1); z += 1.7*(v - u) ----
#pragma unroll
        for (int r = 0; r < 4; r++) {
#pragma unroll
            for (int k = 0; k < 4; k++) {
                float vx = fminf(fmaxf(2.f * u[r][k].x - z[r][k].x, 0.f), 1.f);
                float vy = fminf(fmaxf(2.f * u[r][k].y - z[r][k].y, 0.f), 1.f);
                z[r][k].x = fmaf(1.7f, vx - u[r][k].x, z[r][k].x);
                z[r][k].y = fmaf(1.7f, vy - u[r][k].y, z[r][k].y);
            }
        }
    }

    // ---- store out = p_aff(z_final) = u ----
#pragma unroll
    for (int r = 0; r < 4; r++) {
        float4* o = (float4*)(out + (size_t)(rowbase + r) * DIMV);
        float4 lo, hi;
        lo.x = u[r][0].x; lo.y = u[r][0].y; lo.z = u[r][1].x; lo.w = u[r][1].y;
        hi.x = u[r][2].x; hi.y = u[r][2].y; hi.z = u[r][3].x; hi.w = u[r][3].y;
        o[lane]      = lo;
        o[32 + lane] = hi;
    }
}

// ---------------------------------------------------------------------------
// Launch
// ---------------------------------------------------------------------------
extern "C" void kernel_launch(void* const* d_in, const int* in_sizes, int n_in,
                              void* d_out, int out_size)
{
    const float* x   = (const float*)d_in[0];
    const float* b   = (const float*)d_in[1];
    const float* W1  = (const float*)d_in[2];
    const float* b1  = (const float*)d_in[3];
    const float* W2  = (const float*)d_in[4];
    const float* b2  = (const float*)d_in[5];
    const float* W3  = (const float*)d_in[6];
    const float* b3  = (const float*)d_in[7];
    const float* A   = (const float*)d_in[8];
    const int* n_it  = (const int*)d_in[10];
    float* out = (float*)d_out;

    setup_kernel<<<1, 1024>>>(A);

    float* h1; cudaGetSymbolAddress((void**)&h1, g_H1);
    float* h2; cudaGetSymbolAddress((void**)&h2, g_H2);
    float* y;  cudaGetSymbolAddress((void**)&y,  g_Y);

    gemm_bias_kernel<true ><<<dim3((HID  + 63) / 64, BB / 64), 256>>>(x,  W1, b1, h1, BB, HID,  D_IN);
    gemm_bias_kernel<true ><<<dim3((HID  + 63) / 64, BB / 64), 256>>>(h1, W2, b2, h2, BB, HID,  HID);
    gemm_bias_kernel<false><<<dim3((DIMV + 63) / 64, BB / 64), 256>>>(h2, W3, b3, y,  BB, DIMV, HID);

    cudaFuncSetAttribute(iter_kernel, cudaFuncAttributeMaxDynamicSharedMemorySize, 65536);
    iter_kernel<<<BB / 16, 128, 65536>>>(b, A, n_it, out);
}